// round 1
// baseline (speedup 1.0000x reference)
#include <cuda_runtime.h>
#include <cuda_bf16.h>

// Problem constants
#define S_TOT 4096
#define N_OBJ 32
#define IN_D  4
#define H_D   64
#define IF_D  8
#define SF_D  4
#define OUT_D 2

// Pre-transposed weights (written by prep kernel every launch; deterministic)
__device__ float g_L2Wt[H_D * H_D];   // [k][c] = L2W[c][k]
__device__ float g_I1Wt[H_D * H_D];   // [k][c] = I1W[c][k]
__device__ float g_I2Wt[H_D * IF_D];  // [k][f] = I2W[f][k]

__global__ void magnet_prep(const float* __restrict__ L2W,
                            const float* __restrict__ I1W,
                            const float* __restrict__ I2W) {
    int t = threadIdx.x;
    for (int idx = t; idx < H_D * H_D; idx += blockDim.x) {
        int c = idx >> 6, k = idx & 63;
        g_L2Wt[k * H_D + c] = L2W[idx];
        g_I1Wt[k * H_D + c] = I1W[idx];
    }
    for (int idx = t; idx < IF_D * H_D; idx += blockDim.x) {
        int f = idx >> 6, k = idx & 63;
        g_I2Wt[k * IF_D + f] = I2W[idx];
    }
}

// Fast accurate tanh: 1 - 2/(e^{2x}+1). Error ~1e-7 rel (ex2.approx + rcp.approx).
__device__ __forceinline__ float fast_tanh(float x) {
    x = fminf(fmaxf(x, -15.f), 15.f);          // avoid inf/inf
    float e = __expf(2.f * x);
    return 1.f - __fdividef(2.f, e + 1.f);
}

__global__ __launch_bounds__(1024, 1)
void magnet_main(const float* __restrict__ X,     // [S,32,4]
                 const float* __restrict__ L1W,   // [64,4]
                 const float* __restrict__ L1b,   // [64]
                 const float* __restrict__ L2b,   // [64]
                 const float* __restrict__ I3,    // [992,2,4]
                 const float* __restrict__ S1W,   // [4,4]
                 const float* __restrict__ S1b,   // [4]
                 const float* __restrict__ S2W,   // [32,2,2]
                 const float* __restrict__ S2b,   // [32,2]
                 float* __restrict__ out)         // [S,32,2]
{
    __shared__ float sW[H_D * H_D];       // reused: L2Wt then I1Wt (16 KB)
    __shared__ float sI2[H_D * IF_D];     // [k][f] 2 KB
    __shared__ float sA[N_OBJ * 65];      // stride 65: conflict-free a_j reads
    __shared__ float sB[N_OBJ * 65];
    __shared__ float sX[N_OBJ * IN_D];
    __shared__ float sL1W[H_D * IN_D];
    __shared__ float sL1b[H_D];
    __shared__ float sL2b[H_D];
    __shared__ float sSelf[N_OBJ * OUT_D];

    const int tid  = threadIdx.x;
    const int s    = blockIdx.x;
    const int i    = tid >> 5;
    const int lane = tid & 31;

    // ---- cooperative loads ----
    for (int idx = tid; idx < H_D * H_D; idx += 1024) sW[idx] = g_L2Wt[idx];
    if (tid < H_D * IF_D) sI2[tid] = g_I2Wt[tid];
    if (tid < N_OBJ * IN_D) sX[tid] = X[s * (N_OBJ * IN_D) + tid];
    if (tid >= 512 && tid < 512 + 256) sL1W[tid - 512] = L1W[tid - 512];
    if (tid >= 768 && tid < 768 + 64)  sL1b[tid - 768] = L1b[tid - 768];
    if (tid >= 832 && tid < 832 + 64)  sL2b[tid - 832] = L2b[tid - 832];
    __syncthreads();

    // ---- h1 = relu(x @ L1W^T + L1b) : each thread does channels lane, lane+32 of object i
    {
        float4 xv = ((const float4*)sX)[i];
        float4 w0 = ((const float4*)sL1W)[lane];
        float4 w1 = ((const float4*)sL1W)[lane + 32];
        float a0 = fmaxf(xv.x*w0.x + xv.y*w0.y + xv.z*w0.z + xv.w*w0.w + sL1b[lane], 0.f);
        float a1 = fmaxf(xv.x*w1.x + xv.y*w1.y + xv.z*w1.z + xv.w*w1.w + sL1b[lane + 32], 0.f);
        sA[i * 65 + lane]      = a0;
        sA[i * 65 + lane + 32] = a1;
    }
    __syncthreads();

    // ---- h2 = relu(h1 @ L2W^T + L2b)
    {
        float acc0 = sL2b[lane], acc1 = sL2b[lane + 32];
        #pragma unroll
        for (int k = 0; k < H_D; k++) {
            float h = sA[i * 65 + k];                 // broadcast
            acc0 = fmaf(h, sW[k * H_D + lane],      acc0);
            acc1 = fmaf(h, sW[k * H_D + lane + 32], acc1);
        }
        sB[i * 65 + lane]      = fmaxf(acc0, 0.f);
        sB[i * 65 + lane + 32] = fmaxf(acc1, 0.f);
    }
    __syncthreads();

    // ---- swap weights: sW <- I1Wt ----
    for (int idx = tid; idx < H_D * H_D; idx += 1024) sW[idx] = g_I1Wt[idx];
    __syncthreads();

    // ---- a = h2 @ I1W^T  (key factorization: diff@I1W^T == a_i - a_j)
    {
        float acc0 = 0.f, acc1 = 0.f;
        #pragma unroll
        for (int k = 0; k < H_D; k++) {
            float h = sB[i * 65 + k];
            acc0 = fmaf(h, sW[k * H_D + lane],      acc0);
            acc1 = fmaf(h, sW[k * H_D + lane + 32], acc1);
        }
        sA[i * 65 + lane]      = acc0;
        sA[i * 65 + lane + 32] = acc1;
    }

    // ---- self term (32 threads) : hs = relu(x@S1W^T+S1b); self = einsum + S2b
    if (tid < N_OBJ) {
        float4 xv = ((const float4*)sX)[tid];
        float hs[SF_D];
        #pragma unroll
        for (int f = 0; f < SF_D; f++) {
            float4 w = ((const float4*)S1W)[f];
            hs[f] = fmaxf(xv.x*w.x + xv.y*w.y + xv.z*w.z + xv.w*w.w + S1b[f], 0.f);
        }
        float4 s2 = ((const float4*)S2W)[tid];   // [i][2][2] contiguous
        sSelf[tid * 2 + 0] = hs[0] * s2.x + hs[1] * s2.y + S2b[tid * 2 + 0];
        sSelf[tid * 2 + 1] = hs[2] * s2.z + hs[3] * s2.w + S2b[tid * 2 + 1];
    }
    __syncthreads();

    // ---- pair stage: thread (i, j=lane) ----
    {
        const int j = lane;
        const float* __restrict__ ai = &sA[i * 65];
        const float* __restrict__ aj = &sA[j * 65];   // banks (j+h)%32: conflict-free
        float p0 = 0.f, p1 = 0.f, p2 = 0.f, p3 = 0.f;
        float p4 = 0.f, p5 = 0.f, p6 = 0.f, p7 = 0.f;
        #pragma unroll 16
        for (int h = 0; h < H_D; h++) {
            float t = fast_tanh(ai[h] - aj[h]);
            float4 w0 = ((const float4*)sI2)[h * 2 + 0];   // broadcast
            float4 w1 = ((const float4*)sI2)[h * 2 + 1];
            p0 = fmaf(t, w0.x, p0); p1 = fmaf(t, w0.y, p1);
            p2 = fmaf(t, w0.z, p2); p3 = fmaf(t, w0.w, p3);
            p4 = fmaf(t, w1.x, p4); p5 = fmaf(t, w1.y, p5);
            p6 = fmaf(t, w1.z, p6); p7 = fmaf(t, w1.w, p7);
        }
        float c0 = 0.f, c1 = 0.f;
        if (j != i) {
            int pidx = i * 31 + (j < i ? j : j - 1);   // row-major (i, j!=i)
            const float4* g = (const float4*)(I3 + pidx * 8);
            float4 g0 = g[0], g1 = g[1];
            c0 = fast_tanh(p0)*g0.x + fast_tanh(p1)*g0.y
               + fast_tanh(p2)*g0.z + fast_tanh(p3)*g0.w;
            c1 = fast_tanh(p4)*g1.x + fast_tanh(p5)*g1.y
               + fast_tanh(p6)*g1.z + fast_tanh(p7)*g1.w;
        }
        // warp-reduce over j
        #pragma unroll
        for (int off = 16; off; off >>= 1) {
            c0 += __shfl_xor_sync(0xffffffffu, c0, off);
            c1 += __shfl_xor_sync(0xffffffffu, c1, off);
        }
        if (j == 0) {
            int o = (s * N_OBJ + i) * OUT_D;
            out[o + 0] = c0 + sSelf[i * 2 + 0];
            out[o + 1] = c1 + sSelf[i * 2 + 1];
        }
    }
}

extern "C" void kernel_launch(void* const* d_in, const int* in_sizes, int n_in,
                              void* d_out, int out_size) {
    const float* inputs = (const float*)d_in[0];
    const float* L1W    = (const float*)d_in[1];
    const float* L1b    = (const float*)d_in[2];
    const float* L2W    = (const float*)d_in[3];
    const float* L2b    = (const float*)d_in[4];
    const float* I1W    = (const float*)d_in[5];
    const float* I2W    = (const float*)d_in[6];
    const float* I3     = (const float*)d_in[7];
    const float* S1W    = (const float*)d_in[8];
    const float* S1b    = (const float*)d_in[9];
    const float* S2W    = (const float*)d_in[10];
    const float* S2b    = (const float*)d_in[11];
    float* out = (float*)d_out;

    magnet_prep<<<1, 256>>>(L2W, I1W, I2W);
    magnet_main<<<S_TOT, 1024>>>(inputs, L1W, L1b, L2b, I3,
                                 S1W, S1b, S2W, S2b, out);
}

// round 2
// speedup vs baseline: 1.3423x; 1.3423x over previous
#include <cuda_runtime.h>
#include <cuda_bf16.h>

#define S_TOT 4096
#define N_OBJ 32
#define H_D   64
#define IF_D  8
#define PADF  68   // padded floats per 64-float row (17 float4, conflict-free LDS.128)

// tanh via exp: ~1e-7 rel error (2 MUFU: ex2 + rcp)
__device__ __forceinline__ float fast_tanh(float x) {
    x = fminf(fmaxf(x, -15.f), 15.f);
    float e = __expf(2.f * x);
    return 1.f - __fdividef(2.f, e + 1.f);
}

__global__ __launch_bounds__(1024, 1)
void magnet_main(const float* __restrict__ X,     // [S,32,4]
                 const float* __restrict__ L1W,   // [64,4]
                 const float* __restrict__ L1b,   // [64]
                 const float* __restrict__ L2W,   // [64,64]
                 const float* __restrict__ L2b,   // [64]
                 const float* __restrict__ I1W,   // [64,64]
                 const float* __restrict__ I2W,   // [8,64]
                 const float* __restrict__ I3,    // [992,2,4]
                 const float* __restrict__ S1W,   // [4,4]
                 const float* __restrict__ S1b,   // [4]
                 const float* __restrict__ S2W,   // [32,2,2]
                 const float* __restrict__ S2b,   // [32,2]
                 float* __restrict__ out)         // [S,32,2]
{
    __shared__ __align__(16) float sW[H_D * PADF];        // row-major padded weights (reused)
    __shared__ __align__(16) float bufA[2 * N_OBJ * PADF];
    __shared__ __align__(16) float bufB[2 * N_OBJ * PADF];
    __shared__ __align__(16) float sI2[H_D * IF_D];       // [h][f]
    __shared__ __align__(16) float sX[2 * N_OBJ * 4];
    __shared__ __align__(16) float sL1W[H_D * 4];
    __shared__ float sL1b[H_D];
    __shared__ float sL2b[H_D];
    __shared__ float sRes[2 * N_OBJ * 2];

    const int tid = threadIdx.x;
    const int s0  = blockIdx.x * 2;

    // ---- global -> shared ----
    for (int idx = tid; idx < H_D * H_D; idx += 1024) {
        int c = idx >> 6, k = idx & 63;
        sW[c * PADF + k] = L2W[idx];
    }
    if (tid < 512) {                       // sI2[h*8+f] = I2W[f*64+h]
        int h = tid >> 3, f = tid & 7;
        sI2[tid] = I2W[f * 64 + h];
    }
    if      (tid < 256) sX[tid]          = X[s0 * 128 + tid];
    else if (tid < 512) sL1W[tid - 256]  = L1W[tid - 256];
    else if (tid < 576) sL1b[tid - 512]  = L1b[tid - 512];
    else if (tid < 640) sL2b[tid - 576]  = L2b[tid - 576];
    __syncthreads();

    const int s  = tid >> 9;        // sample within block (0/1)
    const int r  = tid & 511;
    const int io = r >> 4;          // object 0..31
    const int c0 = r & 15;          // base channel; thread does c0, c0+16, c0+32, c0+48

    // ---- h1 = relu(x @ L1W^T + L1b) -> bufA ----
    {
        float4 xv = ((const float4*)sX)[s * N_OBJ + io];
        #pragma unroll
        for (int q = 0; q < 4; q++) {
            int c = c0 + q * 16;
            float4 w = ((const float4*)sL1W)[c];
            float v = fmaf(xv.x, w.x, fmaf(xv.y, w.y,
                      fmaf(xv.z, w.z, fmaf(xv.w, w.w, sL1b[c]))));
            bufA[(s * N_OBJ + io) * PADF + c] = fmaxf(v, 0.f);
        }
    }

    // ---- self term -> sRes (init) ----
    if (tid < 64) {
        int ii = tid & 31;
        float4 xv = ((const float4*)sX)[tid];
        float hs[4];
        #pragma unroll
        for (int f = 0; f < 4; f++) {
            float4 w = ((const float4*)S1W)[f];
            hs[f] = fmaxf(xv.x*w.x + xv.y*w.y + xv.z*w.z + xv.w*w.w + S1b[f], 0.f);
        }
        float4 s2 = ((const float4*)S2W)[ii];
        sRes[tid * 2 + 0] = hs[0] * s2.x + hs[1] * s2.y + S2b[ii * 2 + 0];
        sRes[tid * 2 + 1] = hs[2] * s2.z + hs[3] * s2.w + S2b[ii * 2 + 1];
    }
    __syncthreads();

    // ---- h2 = relu(h1 @ L2W^T + L2b) -> bufB ----
    {
        float acc[4];
        #pragma unroll
        for (int q = 0; q < 4; q++) acc[q] = sL2b[c0 + q * 16];
        const float4* hv = (const float4*)&bufA[(s * N_OBJ + io) * PADF];
        #pragma unroll 4
        for (int k4 = 0; k4 < 16; k4++) {
            float4 h = hv[k4];
            #pragma unroll
            for (int q = 0; q < 4; q++) {
                float4 w = ((const float4*)&sW[(c0 + q * 16) * PADF])[k4];
                acc[q] = fmaf(h.x, w.x, fmaf(h.y, w.y,
                         fmaf(h.z, w.z, fmaf(h.w, w.w, acc[q]))));
            }
        }
        #pragma unroll
        for (int q = 0; q < 4; q++)
            bufB[(s * N_OBJ + io) * PADF + c0 + q * 16] = fmaxf(acc[q], 0.f);
    }
    __syncthreads();

    // ---- swap weights: sW <- I1W (row-major padded) ----
    for (int idx = tid; idx < H_D * H_D; idx += 1024) {
        int c = idx >> 6, k = idx & 63;
        sW[c * PADF + k] = I1W[idx];
    }
    __syncthreads();

    // ---- a = h2 @ I1W^T -> bufA  (diff @ I1W^T == a_i - a_j) ----
    {
        float acc[4] = {0.f, 0.f, 0.f, 0.f};
        const float4* hv = (const float4*)&bufB[(s * N_OBJ + io) * PADF];
        #pragma unroll 4
        for (int k4 = 0; k4 < 16; k4++) {
            float4 h = hv[k4];
            #pragma unroll
            for (int q = 0; q < 4; q++) {
                float4 w = ((const float4*)&sW[(c0 + q * 16) * PADF])[k4];
                acc[q] = fmaf(h.x, w.x, fmaf(h.y, w.y,
                         fmaf(h.z, w.z, fmaf(h.w, w.w, acc[q]))));
            }
        }
        #pragma unroll
        for (int q = 0; q < 4; q++)
            bufA[(s * N_OBJ + io) * PADF + c0 + q * 16] = acc[q];
    }
    __syncthreads();

    // ---- pair stage: thread = one i<j pair of sample s (antisymmetric) ----
    if (r < 496) {
        int i = 0, rem = r;
        while (rem >= 31 - i) { rem -= 31 - i; ++i; }
        int j = i + 1 + rem;

        const float4* ai = (const float4*)&bufA[(s * N_OBJ + i) * PADF];
        const float4* aj = (const float4*)&bufA[(s * N_OBJ + j) * PADF];

        float p0=0.f,p1=0.f,p2=0.f,p3=0.f,p4=0.f,p5=0.f,p6=0.f,p7=0.f;
        #pragma unroll 4
        for (int k4 = 0; k4 < 16; k4++) {
            float4 av = ai[k4], bv = aj[k4];
            float d[4] = {av.x - bv.x, av.y - bv.y, av.z - bv.z, av.w - bv.w};
            #pragma unroll
            for (int u = 0; u < 4; u++) {
                float t = fast_tanh(d[u]);
                int h = k4 * 4 + u;
                float4 w0 = ((const float4*)sI2)[h * 2 + 0];
                float4 w1 = ((const float4*)sI2)[h * 2 + 1];
                p0 = fmaf(t, w0.x, p0); p1 = fmaf(t, w0.y, p1);
                p2 = fmaf(t, w0.z, p2); p3 = fmaf(t, w0.w, p3);
                p4 = fmaf(t, w1.x, p4); p5 = fmaf(t, w1.y, p5);
                p6 = fmaf(t, w1.z, p6); p7 = fmaf(t, w1.w, p7);
            }
        }
        float t0 = fast_tanh(p0), t1 = fast_tanh(p1), t2 = fast_tanh(p2), t3 = fast_tanh(p3);
        float t4 = fast_tanh(p4), t5 = fast_tanh(p5), t6 = fast_tanh(p6), t7 = fast_tanh(p7);

        int idx_ij = i * 31 + (j - 1);   // j > i
        int idx_ji = j * 31 + i;
        const float4* gij = (const float4*)(I3 + idx_ij * 8);
        const float4* gji = (const float4*)(I3 + idx_ji * 8);
        float4 gi0 = __ldg(gij), gi1 = __ldg(gij + 1);
        float4 gj0 = __ldg(gji), gj1 = __ldg(gji + 1);

        float ci0 = t0*gi0.x + t1*gi0.y + t2*gi0.z + t3*gi0.w;
        float ci1 = t4*gi1.x + t5*gi1.y + t6*gi1.z + t7*gi1.w;
        float cj0 = -(t0*gj0.x + t1*gj0.y + t2*gj0.z + t3*gj0.w);
        float cj1 = -(t4*gj1.x + t5*gj1.y + t6*gj1.z + t7*gj1.w);

        atomicAdd(&sRes[(s * N_OBJ + i) * 2 + 0], ci0);
        atomicAdd(&sRes[(s * N_OBJ + i) * 2 + 1], ci1);
        atomicAdd(&sRes[(s * N_OBJ + j) * 2 + 0], cj0);
        atomicAdd(&sRes[(s * N_OBJ + j) * 2 + 1], cj1);
    }
    __syncthreads();

    // ---- write out: 128 floats (2 samples x 32 obj x 2) ----
    if (tid < 64)
        ((float2*)out)[blockIdx.x * 64 + tid] = ((float2*)sRes)[tid];
}

extern "C" void kernel_launch(void* const* d_in, const int* in_sizes, int n_in,
                              void* d_out, int out_size) {
    const float* inputs = (const float*)d_in[0];
    const float* L1W    = (const float*)d_in[1];
    const float* L1b    = (const float*)d_in[2];
    const float* L2W    = (const float*)d_in[3];
    const float* L2b    = (const float*)d_in[4];
    const float* I1W    = (const float*)d_in[5];
    const float* I2W    = (const float*)d_in[6];
    const float* I3     = (const float*)d_in[7];
    const float* S1W    = (const float*)d_in[8];
    const float* S1b    = (const float*)d_in[9];
    const float* S2W    = (const float*)d_in[10];
    const float* S2b    = (const float*)d_in[11];
    float* out = (float*)d_out;

    magnet_main<<<S_TOT / 2, 1024>>>(inputs, L1W, L1b, L2W, L2b,
                                     I1W, I2W, I3, S1W, S1b, S2W, S2b, out);
}